// round 1
// baseline (speedup 1.0000x reference)
#include <cuda_runtime.h>

#define BB 16
#define TT 512
#define HH 1024
#define LL 8192
#define DD 256

typedef unsigned long long ull;

// Scratch for K,V projections: [B,T,D] each, 8 MB. Device globals (no allocs).
__device__ float g_K[BB * TT * DD];
__device__ float g_V[BB * TT * DD];

// ---- f32x2 packed-math helpers (FFMA2 path: 2x fp32 FMA throughput) ----
__device__ __forceinline__ void fma2(ull& d, ull a, ull b) {
    asm("fma.rn.f32x2 %0, %1, %2, %0;" : "+l"(d) : "l"(a), "l"(b));
}
__device__ __forceinline__ ull pack2(float x, float y) {
    ull r;
    asm("mov.b64 %0, {%1, %2};" : "=l"(r)
        : "r"(__float_as_uint(x)), "r"(__float_as_uint(y)));
    return r;
}
__device__ __forceinline__ ull bcast2(float x) {
    ull r;
    asm("mov.b64 %0, {%1, %1};" : "=l"(r) : "r"(__float_as_uint(x)));
    return r;
}
__device__ __forceinline__ float2 unpack2(ull v) {
    float2 f;
    asm("mov.b64 {%0, %1}, %2;" : "=f"(f.x), "=f"(f.y) : "l"(v));
    return f;
}

// ============================================================================
// Kernel A: K = X @ Wk^T, V = X @ Wv^T   (M=B*T=8192, N=D=256, K=H=1024)
// Block: 64(bt) x 64(d) tile, 256 threads, each thread 4x4 for both outputs.
// X tile is read once and shared between the K and V GEMMs.
// ============================================================================
__global__ void __launch_bounds__(256) kv_kernel(const float* __restrict__ X,
                                                 const float* __restrict__ Wk,
                                                 const float* __restrict__ Wv) {
    __shared__ float Xs[16][68];
    __shared__ float As[16][68];
    __shared__ float Bs[16][68];
    const int tid = threadIdx.x;
    const int bm = blockIdx.x * 64;   // bt base
    const int bn = blockIdx.y * 64;   // d base
    const int r  = tid >> 2;          // 0..63
    const int cc = (tid & 3) << 2;    // 0,4,8,12
    const int ty = tid >> 4;          // 0..15 (bt groups)
    const int tx = tid & 15;          // 0..15 (d groups)

    ull aK[4][2], aV[4][2];
#pragma unroll
    for (int i = 0; i < 4; i++) {
        aK[i][0] = aK[i][1] = 0ULL;
        aV[i][0] = aV[i][1] = 0ULL;
    }

    const float* Xp = X  + (size_t)(bm + r) * HH + cc;
    const float* Kp = Wk + (size_t)(bn + r) * HH + cc;
    const float* Vp = Wv + (size_t)(bn + r) * HH + cc;

    for (int h0 = 0; h0 < HH; h0 += 16) {
        float4 xa = *(const float4*)(Xp + h0);
        float4 ka = *(const float4*)(Kp + h0);
        float4 va = *(const float4*)(Vp + h0);
        __syncthreads();
        Xs[cc+0][r] = xa.x; Xs[cc+1][r] = xa.y; Xs[cc+2][r] = xa.z; Xs[cc+3][r] = xa.w;
        As[cc+0][r] = ka.x; As[cc+1][r] = ka.y; As[cc+2][r] = ka.z; As[cc+3][r] = ka.w;
        Bs[cc+0][r] = va.x; Bs[cc+1][r] = va.y; Bs[cc+2][r] = va.z; Bs[cc+3][r] = va.w;
        __syncthreads();
#pragma unroll
        for (int kk = 0; kk < 16; kk++) {
            float4 a4 = *(const float4*)&Xs[kk][ty << 2];
            float4 k4 = *(const float4*)&As[kk][tx << 2];
            float4 v4 = *(const float4*)&Bs[kk][tx << 2];
            ull kp0 = pack2(k4.x, k4.y), kp1 = pack2(k4.z, k4.w);
            ull vp0 = pack2(v4.x, v4.y), vp1 = pack2(v4.z, v4.w);
            float aa[4] = {a4.x, a4.y, a4.z, a4.w};
#pragma unroll
            for (int i = 0; i < 4; i++) {
                ull ab = bcast2(aa[i]);
                fma2(aK[i][0], ab, kp0);
                fma2(aK[i][1], ab, kp1);
                fma2(aV[i][0], ab, vp0);
                fma2(aV[i][1], ab, vp1);
            }
        }
    }
#pragma unroll
    for (int i = 0; i < 4; i++) {
        const int bt = bm + (ty << 2) + i;
        const int d  = bn + (tx << 2);
        float2 k01 = unpack2(aK[i][0]), k23 = unpack2(aK[i][1]);
        float2 v01 = unpack2(aV[i][0]), v23 = unpack2(aV[i][1]);
        *(float4*)&g_K[(size_t)bt * DD + d] = make_float4(k01.x, k01.y, k23.x, k23.y);
        *(float4*)&g_V[(size_t)bt * DD + d] = make_float4(v01.x, v01.y, v23.x, v23.y);
    }
}

// ============================================================================
// Kernel B: fused label-query attention + output projection.
// out[b,l] = sum_t softmax_t(scale*q_l.K[b,t] with mask)[t] * (w_l.V[b,t]) + bias[l]
// Block handles 64 labels for one batch; loops t in chunks of 64, d in chunks
// of 16. Online softmax state (m, num, den) per label in shared memory.
// ============================================================================
__global__ void __launch_bounds__(256) attn_kernel(const float* __restrict__ Q,
                                                   const float* __restrict__ W,
                                                   const float* __restrict__ bias,
                                                   const int* __restrict__ mask,
                                                   float* __restrict__ out) {
    __shared__ float Qs[16][68];
    __shared__ float Ws[16][68];
    __shared__ float Ks[16][68];
    __shared__ float Vs[16][68];
    __shared__ float m_s[64], num_s[64], den_s[64];

    const int tid = threadIdx.x;
    const int b  = blockIdx.y;
    const int l0 = blockIdx.x * 64;
    const int r  = tid >> 2;
    const int cc = (tid & 3) << 2;
    const int ty = tid >> 4;   // label group 0..15
    const int tx = tid & 15;   // t group 0..15

    if (tid < 64) { m_s[tid] = -1e30f; num_s[tid] = 0.0f; den_s[tid] = 0.0f; }

    const float* Qp = Q + (size_t)(l0 + r) * DD + cc;
    const float* Wp = W + (size_t)(l0 + r) * DD + cc;
    const float* KBase = g_K + (size_t)b * TT * DD;
    const float* VBase = g_V + (size_t)b * TT * DD;
    const float scale = 0.0625f;  // 1/sqrt(256)

    for (int t0 = 0; t0 < TT; t0 += 64) {
        ull zp[4][2], sp[4][2];
#pragma unroll
        for (int i = 0; i < 4; i++) {
            zp[i][0] = zp[i][1] = 0ULL;
            sp[i][0] = sp[i][1] = 0ULL;
        }
        const float* Kp = KBase + (size_t)(t0 + r) * DD + cc;
        const float* Vp = VBase + (size_t)(t0 + r) * DD + cc;

        for (int d0 = 0; d0 < DD; d0 += 16) {
            float4 qa = *(const float4*)(Qp + d0);
            float4 wa = *(const float4*)(Wp + d0);
            float4 ka = *(const float4*)(Kp + d0);
            float4 va = *(const float4*)(Vp + d0);
            __syncthreads();
            Qs[cc+0][r] = qa.x; Qs[cc+1][r] = qa.y; Qs[cc+2][r] = qa.z; Qs[cc+3][r] = qa.w;
            Ws[cc+0][r] = wa.x; Ws[cc+1][r] = wa.y; Ws[cc+2][r] = wa.z; Ws[cc+3][r] = wa.w;
            Ks[cc+0][r] = ka.x; Ks[cc+1][r] = ka.y; Ks[cc+2][r] = ka.z; Ks[cc+3][r] = ka.w;
            Vs[cc+0][r] = va.x; Vs[cc+1][r] = va.y; Vs[cc+2][r] = va.z; Vs[cc+3][r] = va.w;
            __syncthreads();
#pragma unroll
            for (int kk = 0; kk < 16; kk++) {
                float4 q4 = *(const float4*)&Qs[kk][ty << 2];
                float4 w4 = *(const float4*)&Ws[kk][ty << 2];
                float4 k4 = *(const float4*)&Ks[kk][tx << 2];
                float4 v4 = *(const float4*)&Vs[kk][tx << 2];
                ull kp0 = pack2(k4.x, k4.y), kp1 = pack2(k4.z, k4.w);
                ull vp0 = pack2(v4.x, v4.y), vp1 = pack2(v4.z, v4.w);
                float qq[4] = {q4.x, q4.y, q4.z, q4.w};
                float ww[4] = {w4.x, w4.y, w4.z, w4.w};
#pragma unroll
                for (int i = 0; i < 4; i++) {
                    ull qb = bcast2(qq[i]);
                    ull wb = bcast2(ww[i]);
                    fma2(zp[i][0], qb, kp0);
                    fma2(zp[i][1], qb, kp1);
                    fma2(sp[i][0], wb, vp0);
                    fma2(sp[i][1], wb, vp1);
                }
            }
        }
        // ---- mask + scale + online softmax update over this 64-wide t chunk ----
        const int tb = b * TT + t0 + (tx << 2);
        const int mv0 = mask[tb + 0];
        const int mv1 = mask[tb + 1];
        const int mv2 = mask[tb + 2];
        const int mv3 = mask[tb + 3];
#pragma unroll
        for (int i = 0; i < 4; i++) {
            float2 z01 = unpack2(zp[i][0]), z23 = unpack2(zp[i][1]);
            float2 s01 = unpack2(sp[i][0]), s23 = unpack2(sp[i][1]);
            float zz0 = mv0 ? z01.x * scale : -1e30f;
            float zz1 = mv1 ? z01.y * scale : -1e30f;
            float zz2 = mv2 ? z23.x * scale : -1e30f;
            float zz3 = mv3 ? z23.y * scale : -1e30f;
            float tm = fmaxf(fmaxf(zz0, zz1), fmaxf(zz2, zz3));
#pragma unroll
            for (int off = 8; off >= 1; off >>= 1)
                tm = fmaxf(tm, __shfl_xor_sync(0xffffffffu, tm, off));
            float e0 = __expf(zz0 - tm), e1 = __expf(zz1 - tm);
            float e2 = __expf(zz2 - tm), e3 = __expf(zz3 - tm);
            float pe = e0 + e1 + e2 + e3;
            float ps = e0 * s01.x + e1 * s01.y + e2 * s23.x + e3 * s23.y;
#pragma unroll
            for (int off = 8; off >= 1; off >>= 1) {
                pe += __shfl_xor_sync(0xffffffffu, pe, off);
                ps += __shfl_xor_sync(0xffffffffu, ps, off);
            }
            if (tx == 0) {
                const int l = (ty << 2) + i;
                float mo = m_s[l];
                float mn = fmaxf(mo, tm);
                float eo = __expf(mo - mn);
                float en = __expf(tm - mn);
                num_s[l] = num_s[l] * eo + ps * en;
                den_s[l] = den_s[l] * eo + pe * en;
                m_s[l] = mn;
            }
        }
    }
    __syncthreads();
    if (tid < 64) {
        out[(size_t)b * LL + l0 + tid] = num_s[tid] / den_s[tid] + bias[l0 + tid];
    }
}

extern "C" void kernel_launch(void* const* d_in, const int* in_sizes, int n_in,
                              void* d_out, int out_size) {
    const float* X       = (const float*)d_in[0];
    const int*   mask    = (const int*)d_in[1];
    const float* queries = (const float*)d_in[2];
    const float* Wk      = (const float*)d_in[3];
    const float* Wv      = (const float*)d_in[4];
    const float* out_w   = (const float*)d_in[5];
    const float* out_b   = (const float*)d_in[6];
    float* out = (float*)d_out;

    dim3 gA(128, 4);   // (B*T)/64 x D/64
    kv_kernel<<<gA, 256>>>(X, Wk, Wv);

    dim3 gB(128, 16);  // L/64 x B
    attn_kernel<<<gB, 256>>>(queries, out_w, out_b, mask, out);
}

// round 2
// speedup vs baseline: 1.0012x; 1.0012x over previous
#include <cuda_runtime.h>

#define BB 16
#define TT 512
#define HH 1024
#define LL 8192
#define DD 256

typedef unsigned long long ull;

// Scratch for K,V projections: [B,T,D] each, 8 MB. Device globals (no allocs).
__device__ float g_K[BB * TT * DD];
__device__ float g_V[BB * TT * DD];

// ---- f32x2 packed-math helpers (FFMA2 path: 2x fp32 FMA throughput) ----
__device__ __forceinline__ void fma2(ull& d, ull a, ull b) {
    asm("fma.rn.f32x2 %0, %1, %2, %0;" : "+l"(d) : "l"(a), "l"(b));
}
__device__ __forceinline__ ull pack2(float x, float y) {
    ull r;
    asm("mov.b64 %0, {%1, %2};" : "=l"(r)
        : "r"(__float_as_uint(x)), "r"(__float_as_uint(y)));
    return r;
}
__device__ __forceinline__ ull bcast2(float x) {
    ull r;
    asm("mov.b64 %0, {%1, %1};" : "=l"(r) : "r"(__float_as_uint(x)));
    return r;
}
__device__ __forceinline__ float2 unpack2(ull v) {
    float2 f;
    asm("mov.b64 {%0, %1}, %2;" : "=f"(f.x), "=f"(f.y) : "l"(v));
    return f;
}

// ============================================================================
// Kernel A: K = X @ Wk^T, V = X @ Wv^T   (M=B*T=8192, N=D=256, K=H=1024)
// Block: 64(bt) x 64(d) tile, 256 threads, each thread 4x4 for both outputs.
// X tile is read once and shared between the K and V GEMMs.
// ============================================================================
__global__ void __launch_bounds__(256) kv_kernel(const float* __restrict__ X,
                                                 const float* __restrict__ Wk,
                                                 const float* __restrict__ Wv) {
    __shared__ float Xs[16][68];
    __shared__ float As[16][68];
    __shared__ float Bs[16][68];
    const int tid = threadIdx.x;
    const int bm = blockIdx.x * 64;   // bt base
    const int bn = blockIdx.y * 64;   // d base
    const int r  = tid >> 2;          // 0..63
    const int cc = (tid & 3) << 2;    // 0,4,8,12
    const int ty = tid >> 4;          // 0..15 (bt groups)
    const int tx = tid & 15;          // 0..15 (d groups)

    ull aK[4][2], aV[4][2];
#pragma unroll
    for (int i = 0; i < 4; i++) {
        aK[i][0] = aK[i][1] = 0ULL;
        aV[i][0] = aV[i][1] = 0ULL;
    }

    const float* Xp = X  + (size_t)(bm + r) * HH + cc;
    const float* Kp = Wk + (size_t)(bn + r) * HH + cc;
    const float* Vp = Wv + (size_t)(bn + r) * HH + cc;

    for (int h0 = 0; h0 < HH; h0 += 16) {
        float4 xa = *(const float4*)(Xp + h0);
        float4 ka = *(const float4*)(Kp + h0);
        float4 va = *(const float4*)(Vp + h0);
        __syncthreads();
        Xs[cc+0][r] = xa.x; Xs[cc+1][r] = xa.y; Xs[cc+2][r] = xa.z; Xs[cc+3][r] = xa.w;
        As[cc+0][r] = ka.x; As[cc+1][r] = ka.y; As[cc+2][r] = ka.z; As[cc+3][r] = ka.w;
        Bs[cc+0][r] = va.x; Bs[cc+1][r] = va.y; Bs[cc+2][r] = va.z; Bs[cc+3][r] = va.w;
        __syncthreads();
#pragma unroll
        for (int kk = 0; kk < 16; kk++) {
            float4 a4 = *(const float4*)&Xs[kk][ty << 2];
            float4 k4 = *(const float4*)&As[kk][tx << 2];
            float4 v4 = *(const float4*)&Bs[kk][tx << 2];
            ull kp0 = pack2(k4.x, k4.y), kp1 = pack2(k4.z, k4.w);
            ull vp0 = pack2(v4.x, v4.y), vp1 = pack2(v4.z, v4.w);
            float aa[4] = {a4.x, a4.y, a4.z, a4.w};
#pragma unroll
            for (int i = 0; i < 4; i++) {
                ull ab = bcast2(aa[i]);
                fma2(aK[i][0], ab, kp0);
                fma2(aK[i][1], ab, kp1);
                fma2(aV[i][0], ab, vp0);
                fma2(aV[i][1], ab, vp1);
            }
        }
    }
#pragma unroll
    for (int i = 0; i < 4; i++) {
        const int bt = bm + (ty << 2) + i;
        const int d  = bn + (tx << 2);
        float2 k01 = unpack2(aK[i][0]), k23 = unpack2(aK[i][1]);
        float2 v01 = unpack2(aV[i][0]), v23 = unpack2(aV[i][1]);
        *(float4*)&g_K[(size_t)bt * DD + d] = make_float4(k01.x, k01.y, k23.x, k23.y);
        *(float4*)&g_V[(size_t)bt * DD + d] = make_float4(v01.x, v01.y, v23.x, v23.y);
    }
}

// ============================================================================
// Kernel B: fused label-query attention + output projection.
// out[b,l] = sum_t softmax_t(scale*q_l.K[b,t] with mask)[t] * (w_l.V[b,t]) + bias[l]
// Block handles 64 labels for one batch; loops t in chunks of 64, d in chunks
// of 16. Online softmax state (m, num, den) per label in shared memory.
// ============================================================================
__global__ void __launch_bounds__(256) attn_kernel(const float* __restrict__ Q,
                                                   const float* __restrict__ W,
                                                   const float* __restrict__ bias,
                                                   const int* __restrict__ mask,
                                                   float* __restrict__ out) {
    __shared__ float Qs[16][68];
    __shared__ float Ws[16][68];
    __shared__ float Ks[16][68];
    __shared__ float Vs[16][68];
    __shared__ float m_s[64], num_s[64], den_s[64];

    const int tid = threadIdx.x;
    const int b  = blockIdx.y;
    const int l0 = blockIdx.x * 64;
    const int r  = tid >> 2;
    const int cc = (tid & 3) << 2;
    const int ty = tid >> 4;   // label group 0..15
    const int tx = tid & 15;   // t group 0..15

    if (tid < 64) { m_s[tid] = -1e30f; num_s[tid] = 0.0f; den_s[tid] = 0.0f; }

    const float* Qp = Q + (size_t)(l0 + r) * DD + cc;
    const float* Wp = W + (size_t)(l0 + r) * DD + cc;
    const float* KBase = g_K + (size_t)b * TT * DD;
    const float* VBase = g_V + (size_t)b * TT * DD;
    const float scale = 0.0625f;  // 1/sqrt(256)

    for (int t0 = 0; t0 < TT; t0 += 64) {
        ull zp[4][2], sp[4][2];
#pragma unroll
        for (int i = 0; i < 4; i++) {
            zp[i][0] = zp[i][1] = 0ULL;
            sp[i][0] = sp[i][1] = 0ULL;
        }
        const float* Kp = KBase + (size_t)(t0 + r) * DD + cc;
        const float* Vp = VBase + (size_t)(t0 + r) * DD + cc;

        for (int d0 = 0; d0 < DD; d0 += 16) {
            float4 qa = *(const float4*)(Qp + d0);
            float4 wa = *(const float4*)(Wp + d0);
            float4 ka = *(const float4*)(Kp + d0);
            float4 va = *(const float4*)(Vp + d0);
            __syncthreads();
            Qs[cc+0][r] = qa.x; Qs[cc+1][r] = qa.y; Qs[cc+2][r] = qa.z; Qs[cc+3][r] = qa.w;
            Ws[cc+0][r] = wa.x; Ws[cc+1][r] = wa.y; Ws[cc+2][r] = wa.z; Ws[cc+3][r] = wa.w;
            Ks[cc+0][r] = ka.x; Ks[cc+1][r] = ka.y; Ks[cc+2][r] = ka.z; Ks[cc+3][r] = ka.w;
            Vs[cc+0][r] = va.x; Vs[cc+1][r] = va.y; Vs[cc+2][r] = va.z; Vs[cc+3][r] = va.w;
            __syncthreads();
#pragma unroll
            for (int kk = 0; kk < 16; kk++) {
                float4 q4 = *(const float4*)&Qs[kk][ty << 2];
                float4 w4 = *(const float4*)&Ws[kk][ty << 2];
                float4 k4 = *(const float4*)&Ks[kk][tx << 2];
                float4 v4 = *(const float4*)&Vs[kk][tx << 2];
                ull kp0 = pack2(k4.x, k4.y), kp1 = pack2(k4.z, k4.w);
                ull vp0 = pack2(v4.x, v4.y), vp1 = pack2(v4.z, v4.w);
                float qq[4] = {q4.x, q4.y, q4.z, q4.w};
                float ww[4] = {w4.x, w4.y, w4.z, w4.w};
#pragma unroll
                for (int i = 0; i < 4; i++) {
                    ull qb = bcast2(qq[i]);
                    ull wb = bcast2(ww[i]);
                    fma2(zp[i][0], qb, kp0);
                    fma2(zp[i][1], qb, kp1);
                    fma2(sp[i][0], wb, vp0);
                    fma2(sp[i][1], wb, vp1);
                }
            }
        }
        // ---- mask + scale + online softmax update over this 64-wide t chunk ----
        const int tb = b * TT + t0 + (tx << 2);
        const int mv0 = mask[tb + 0];
        const int mv1 = mask[tb + 1];
        const int mv2 = mask[tb + 2];
        const int mv3 = mask[tb + 3];
#pragma unroll
        for (int i = 0; i < 4; i++) {
            float2 z01 = unpack2(zp[i][0]), z23 = unpack2(zp[i][1]);
            float2 s01 = unpack2(sp[i][0]), s23 = unpack2(sp[i][1]);
            float zz0 = mv0 ? z01.x * scale : -1e30f;
            float zz1 = mv1 ? z01.y * scale : -1e30f;
            float zz2 = mv2 ? z23.x * scale : -1e30f;
            float zz3 = mv3 ? z23.y * scale : -1e30f;
            float tm = fmaxf(fmaxf(zz0, zz1), fmaxf(zz2, zz3));
#pragma unroll
            for (int off = 8; off >= 1; off >>= 1)
                tm = fmaxf(tm, __shfl_xor_sync(0xffffffffu, tm, off));
            float e0 = __expf(zz0 - tm), e1 = __expf(zz1 - tm);
            float e2 = __expf(zz2 - tm), e3 = __expf(zz3 - tm);
            float pe = e0 + e1 + e2 + e3;
            float ps = e0 * s01.x + e1 * s01.y + e2 * s23.x + e3 * s23.y;
#pragma unroll
            for (int off = 8; off >= 1; off >>= 1) {
                pe += __shfl_xor_sync(0xffffffffu, pe, off);
                ps += __shfl_xor_sync(0xffffffffu, ps, off);
            }
            if (tx == 0) {
                const int l = (ty << 2) + i;
                float mo = m_s[l];
                float mn = fmaxf(mo, tm);
                float eo = __expf(mo - mn);
                float en = __expf(tm - mn);
                num_s[l] = num_s[l] * eo + ps * en;
                den_s[l] = den_s[l] * eo + pe * en;
                m_s[l] = mn;
            }
        }
    }
    __syncthreads();
    if (tid < 64) {
        out[(size_t)b * LL + l0 + tid] = num_s[tid] / den_s[tid] + bias[l0 + tid];
    }
}

extern "C" void kernel_launch(void* const* d_in, const int* in_sizes, int n_in,
                              void* d_out, int out_size) {
    const float* X       = (const float*)d_in[0];
    const int*   mask    = (const int*)d_in[1];
    const float* queries = (const float*)d_in[2];
    const float* Wk      = (const float*)d_in[3];
    const float* Wv      = (const float*)d_in[4];
    const float* out_w   = (const float*)d_in[5];
    const float* out_b   = (const float*)d_in[6];
    float* out = (float*)d_out;

    dim3 gA(128, 4);   // (B*T)/64 x D/64
    kv_kernel<<<gA, 256>>>(X, Wk, Wv);

    dim3 gB(128, 16);  // L/64 x B
    attn_kernel<<<gB, 256>>>(queries, out_w, out_b, mask, out);
}